// round 1
// baseline (speedup 1.0000x reference)
#include <cuda_runtime.h>
#include <cuda_bf16.h>

// Scratch: per-batch class-presence bitmasks (graph-capturable, no allocs).
__device__ unsigned int g_masks[64];

#define PRES_THREADS 256
#define BLOCKS_PER_BATCH 64

__global__ void init_masks_kernel(int B) {
    int t = threadIdx.x;
    if (t < B) g_masks[t] = 0u;
}

// Presence kernel: grid = (BLOCKS_PER_BATCH, B). Each block owns a contiguous
// chunk of one batch's targets. It first samples 2 strided int4 iterations
// (2048 ints). If that sample already contains every class, the rest of the
// chunk cannot change the (monotone) presence mask, so it is skipped.
// The skip decision depends only on this block's own input data: same inputs
// -> same work -> same output.
__global__ void presence_kernel(const int* __restrict__ targets,
                                int total4, int tail, int n_per_batch,
                                unsigned int full_mask) {
    const int b = blockIdx.y;
    const int4* __restrict__ t4 =
        reinterpret_cast<const int4*>(targets + (long long)b * n_per_batch);

    const int chunk4 = (total4 + gridDim.x - 1) / gridDim.x;
    const int start  = blockIdx.x * chunk4;
    const int end    = min(start + chunk4, total4);

    unsigned int m = 0u;
    int i = start + threadIdx.x;

    // --- sample phase: 2 strided iterations (2048 ints per block) ---
    #pragma unroll
    for (int s = 0; s < 2; s++) {
        if (i < end) {
            int4 v = t4[i];
            m |= (1u << (v.x & 31)) | (1u << (v.y & 31)) |
                 (1u << (v.z & 31)) | (1u << (v.w & 31));
        }
        i += blockDim.x;
    }

    __shared__ unsigned int smask;
    if (threadIdx.x == 0) smask = 0u;
    __syncthreads();

    unsigned int wm = __reduce_or_sync(0xffffffffu, m);
    if ((threadIdx.x & 31) == 0) atomicOr(&smask, wm);
    __syncthreads();

    if ((smask & full_mask) == full_mask) {
        // Mask already saturated: remaining elements cannot change it.
        if (threadIdx.x == 0) atomicOr(&g_masks[b], full_mask);
        return;
    }

    // --- full scan of the remaining chunk ---
    for (; i < end; i += blockDim.x) {
        int4 v = t4[i];
        m |= (1u << (v.x & 31)) | (1u << (v.y & 31)) |
             (1u << (v.z & 31)) | (1u << (v.w & 31));
    }

    // Scalar tail (non-multiple-of-4 element counts), handled by last block.
    if (blockIdx.x == gridDim.x - 1 && threadIdx.x < tail) {
        int v = targets[(long long)b * n_per_batch + total4 * 4 + threadIdx.x];
        m |= (1u << (v & 31));
    }

    wm = __reduce_or_sync(0xffffffffu, m);
    if ((threadIdx.x & 31) == 0) atomicOr(&smask, wm);
    __syncthreads();

    if (threadIdx.x == 0) atomicOr(&g_masks[b], smask & full_mask);
}

// Loss kernel: 1 block. BCE(sigmoid(preds), presence) with mean reduction,
// via numerically stable log-sigmoid: logsig(x) = min(x,0) - log1p(exp(-|x|)).
__global__ void loss_kernel(const float* __restrict__ preds,
                            float* __restrict__ out, int B, int C) {
    const int n = B * C;
    float acc = 0.0f;
    for (int i = threadIdx.x; i < n; i += blockDim.x) {
        const int b = i / C;
        const int c = i - b * C;
        const float x = preds[i];
        const float y = ((g_masks[b] >> c) & 1u) ? 1.0f : 0.0f;
        const float l = log1pf(expf(-fabsf(x)));   // = -logsig(|x|)
        const float lsp = fminf(x, 0.0f) - l;      // logsig(x)
        const float lsn = fminf(-x, 0.0f) - l;     // logsig(-x)
        acc += -(y * lsp + (1.0f - y) * lsn);
    }

    // Block reduction (blockDim.x = 512 -> 16 warps)
    __shared__ float warp_sums[16];
    for (int off = 16; off > 0; off >>= 1)
        acc += __shfl_down_sync(0xffffffffu, acc, off);
    const int wid = threadIdx.x >> 5;
    if ((threadIdx.x & 31) == 0) warp_sums[wid] = acc;
    __syncthreads();
    if (threadIdx.x < 32) {
        float v = (threadIdx.x < (blockDim.x >> 5)) ? warp_sums[threadIdx.x] : 0.0f;
        for (int off = 16; off > 0; off >>= 1)
            v += __shfl_down_sync(0xffffffffu, v, off);
        if (threadIdx.x == 0) out[0] = v / (float)n;
    }
}

extern "C" void kernel_launch(void* const* d_in, const int* in_sizes, int n_in,
                              void* d_out, int out_size) {
    const float* preds   = (const float*)d_in[0];
    const int*   targets = (const int*)d_in[1];

    const int C = 19;                         // NUM_CLASSES (fixed by problem)
    const int B = in_sizes[0] / C;            // 16
    const int n_total     = in_sizes[1];      // B*H*W
    const int n_per_batch = n_total / B;
    const int total4      = n_per_batch / 4;
    const int tail        = n_per_batch - total4 * 4;
    const unsigned int full_mask = (1u << C) - 1u;

    init_masks_kernel<<<1, 64>>>(B);

    dim3 grid(BLOCKS_PER_BATCH, B);
    presence_kernel<<<grid, PRES_THREADS>>>(targets, total4, tail,
                                            n_per_batch, full_mask);

    loss_kernel<<<1, 512>>>(preds, (float*)d_out, B, C);
}

// round 2
// speedup vs baseline: 1.0646x; 1.0646x over previous
#include <cuda_runtime.h>
#include <cuda_bf16.h>

// Single fused kernel, single block. The whole problem after the presence
// observation is tiny:
//   - presence of each class per batch (monotone OR over 2M labels/batch)
//   - 304 BCE terms + mean
// Presence is decided from a 2048-element sampled prefix per batch; if the
// sampled mask is already full (prob of miss ~1e-46 per batch for this data),
// the remaining labels provably cannot change it. Any batch whose sample is
// incomplete is fully scanned (correct for arbitrary inputs, just slower).
// Decision depends only on input data: same inputs -> same work -> same output.

#define MAX_B 64

__global__ void fused_segenc_loss_kernel(const float* __restrict__ preds,
                                         const int*   __restrict__ targets,
                                         float* __restrict__ out,
                                         int B, int C, int n_per_batch) {
    __shared__ unsigned int smask[MAX_B];
    __shared__ float warp_sums[32];

    const int t = threadIdx.x;
    const int b = t >> 6;          // 64 threads per batch for sampling
    const int j = t & 63;
    const unsigned int full_mask = (1u << C) - 1u;
    const bool vec_ok = ((n_per_batch & 3) == 0);
    const int total4 = n_per_batch >> 2;

    if (t < B) smask[t] = 0u;
    __syncthreads();

    // ---- sample phase: coalesced prefix, 64 thr x 8 int4 = 2048 ints/batch
    unsigned int m = 0u;
    if (b < B && vec_ok) {
        const int4* __restrict__ t4 =
            reinterpret_cast<const int4*>(targets) + (long long)b * total4;
        const int limit = min(512, total4);
        #pragma unroll
        for (int k = 0; k < 8; k++) {
            const int idx = j + (k << 6);
            if (idx < limit) {
                const int4 v = t4[idx];
                m |= (1u << (v.x & 31)) | (1u << (v.y & 31)) |
                     (1u << (v.z & 31)) | (1u << (v.w & 31));
            }
        }
    }
    {
        const unsigned int wm = __reduce_or_sync(0xffffffffu, m);
        if ((t & 31) == 0 && b < B) atomicOr(&smask[b], wm);
    }
    __syncthreads();

    // ---- fallback: full scalar scan of any batch whose sample is incomplete.
    // Condition reads shared state -> block-uniform; __syncthreads inside is ok.
    for (int bb = 0; bb < B; bb++) {
        if ((smask[bb] & full_mask) != full_mask) {
            unsigned int mm = 0u;
            const int* __restrict__ tb = targets + (long long)bb * n_per_batch;
            for (int i = t; i < n_per_batch; i += blockDim.x)
                mm |= 1u << (tb[i] & 31);
            const unsigned int wm = __reduce_or_sync(0xffffffffu, mm);
            if ((t & 31) == 0) atomicOr(&smask[bb], wm);
            __syncthreads();
        }
    }
    __syncthreads();

    // ---- loss: BCE(sigmoid(preds), presence), stable log-sigmoid, mean.
    const int n = B * C;
    float acc = 0.0f;
    for (int i = t; i < n; i += blockDim.x) {
        const int ib = i / C;
        const int ic = i - ib * C;
        const float x = preds[i];
        const float y = ((smask[ib] >> ic) & 1u) ? 1.0f : 0.0f;
        const float l   = log1pf(expf(-fabsf(x)));  // = -logsig(|x|)
        const float lsp = fminf(x, 0.0f) - l;       // logsig(x)
        const float lsn = fminf(-x, 0.0f) - l;      // logsig(-x)
        acc += -(y * lsp + (1.0f - y) * lsn);
    }

    // ---- block reduction (up to 32 warps)
    for (int off = 16; off > 0; off >>= 1)
        acc += __shfl_down_sync(0xffffffffu, acc, off);
    if ((t & 31) == 0) warp_sums[t >> 5] = acc;
    __syncthreads();
    if (t < 32) {
        const int nw = blockDim.x >> 5;
        float v = (t < nw) ? warp_sums[t] : 0.0f;
        for (int off = 16; off > 0; off >>= 1)
            v += __shfl_down_sync(0xffffffffu, v, off);
        if (t == 0) out[0] = v / (float)n;
    }
}

extern "C" void kernel_launch(void* const* d_in, const int* in_sizes, int n_in,
                              void* d_out, int out_size) {
    const float* preds   = (const float*)d_in[0];
    const int*   targets = (const int*)d_in[1];

    const int C = 19;                       // NUM_CLASSES (fixed by problem)
    const int B = in_sizes[0] / C;          // 16
    const int n_per_batch = in_sizes[1] / B;

    int threads = B * 64;
    if (threads < 256)  threads = 256;
    if (threads > 1024) threads = 1024;

    fused_segenc_loss_kernel<<<1, threads>>>(preds, targets, (float*)d_out,
                                             B, C, n_per_batch);
}

// round 3
// speedup vs baseline: 1.3023x; 1.2233x over previous
#include <cuda_runtime.h>
#include <cuda_bf16.h>

// Single fused kernel, single block, cycle-count-optimized (GPU runs at idle
// clock during graph replay, so the wall time is critical-path cycles).
//
// Presence per batch is decided from a 1024-element sampled prefix; if the
// sampled mask is already full, the remaining labels provably cannot change
// the (monotone) OR. Miss prob ~2e-23/batch on random labels; any batch whose
// sample is incomplete is fully scanned (correct for arbitrary inputs).
// Decision depends only on input data: same inputs -> same work -> same output.
//
// Cycle-path tricks:
//  - BCE log-sigmoid terms (expf/log1pf chain) computed from preds BEFORE the
//    targets loads resolve -> transcendentals fully overlap DRAM latency;
//    after the mask arrives the loss is a select+add.
//  - all-batches-saturated check is one __syncthreads_and (parallel), not a
//    serial 16-iteration shared-load loop.

#define MAX_B 64

__global__ void fused_segenc_loss_kernel(const float* __restrict__ preds,
                                         const int*   __restrict__ targets,
                                         float* __restrict__ out,
                                         int B, int C, int n_per_batch) {
    __shared__ unsigned int smask[MAX_B];
    __shared__ float warp_sums[32];

    const int t = threadIdx.x;
    const int b = t >> 6;          // 64 threads per batch for sampling
    const int j = t & 63;
    const unsigned int full_mask = (1u << C) - 1u;
    const bool vec_ok = ((n_per_batch & 3) == 0);
    const int total4 = n_per_batch >> 2;
    const int n = B * C;

    if (t < MAX_B) smask[t] = 0u;

    // ---- issue targets loads first (longest latency) ----
    // 64 thr/batch x 4 int4 = 1024 sampled ints per batch, coalesced prefix.
    unsigned int m = 0u;
    if (b < B && vec_ok) {
        const int4* __restrict__ t4 =
            reinterpret_cast<const int4*>(targets) + (long long)b * total4;
        const int limit = min(256, total4);
        #pragma unroll
        for (int k = 0; k < 4; k++) {
            const int idx = j + (k << 6);
            if (idx < limit) {
                const int4 v = t4[idx];
                m |= (1u << (v.x & 31)) | (1u << (v.y & 31)) |
                     (1u << (v.z & 31)) | (1u << (v.w & 31));
            }
        }
    }

    // ---- overlap: preds load + stable log-sigmoid pieces (mask-independent)
    float lsp = 0.0f, lsn = 0.0f;
    int ib = 0;
    const bool has_elem = (t < n);
    if (has_elem) {
        const float x = preds[t];
        ib = t / C;
        const float l = log1pf(expf(-fabsf(x)));   // = -logsig(|x|)
        lsp = fminf(x, 0.0f) - l;                  // logsig(x)
        lsn = fminf(-x, 0.0f) - l;                 // logsig(-x)
    }

    __syncthreads();   // smask init visible

    {
        const unsigned int wm = __reduce_or_sync(0xffffffffu, m);
        if ((t & 31) == 0 && b < B) atomicOr(&smask[b], wm);
    }
    __syncthreads();

    // ---- parallel saturation check: one barrier op, no serial LDS chain ----
    const int my_ok = (t < B) ? ((smask[t] & full_mask) == full_mask) : 1;
    if (!__syncthreads_and(my_ok)) {
        // Rare fallback: full scalar scan of incomplete batches (block-uniform
        // control flow: condition reads post-sync shared state).
        for (int bb = 0; bb < B; bb++) {
            if ((smask[bb] & full_mask) != full_mask) {
                unsigned int mm = 0u;
                const int* __restrict__ tb = targets + (long long)bb * n_per_batch;
                for (int i = t; i < n_per_batch; i += blockDim.x)
                    mm |= 1u << (tb[i] & 31);
                const unsigned int wm = __reduce_or_sync(0xffffffffu, mm);
                if ((t & 31) == 0) atomicOr(&smask[bb], wm);
                __syncthreads();
            }
        }
        __syncthreads();
    }

    // ---- loss: select precomputed pieces by presence bit, then reduce ----
    float acc = 0.0f;
    if (has_elem) {
        const int ic = t - ib * C;
        acc = -(((smask[ib] >> ic) & 1u) ? lsp : lsn);
    }
    // Generality: elements beyond blockDim (only if B*C > blockDim).
    for (int i = t + blockDim.x; i < n; i += blockDim.x) {
        const int ib2 = i / C;
        const int ic2 = i - ib2 * C;
        const float x = preds[i];
        const float l = log1pf(expf(-fabsf(x)));
        const float p = fminf(x, 0.0f) - l;
        const float q = fminf(-x, 0.0f) - l;
        acc += -(((smask[ib2] >> ic2) & 1u) ? p : q);
    }

    // ---- block reduction (32 warps) ----
    for (int off = 16; off > 0; off >>= 1)
        acc += __shfl_down_sync(0xffffffffu, acc, off);
    if ((t & 31) == 0) warp_sums[t >> 5] = acc;
    __syncthreads();
    if (t < 32) {
        const int nw = blockDim.x >> 5;
        float v = (t < nw) ? warp_sums[t] : 0.0f;
        for (int off = 16; off > 0; off >>= 1)
            v += __shfl_down_sync(0xffffffffu, v, off);
        if (t == 0) out[0] = v / (float)n;
    }
}

extern "C" void kernel_launch(void* const* d_in, const int* in_sizes, int n_in,
                              void* d_out, int out_size) {
    const float* preds   = (const float*)d_in[0];
    const int*   targets = (const int*)d_in[1];

    const int C = 19;                       // NUM_CLASSES (fixed by problem)
    const int B = in_sizes[0] / C;          // 16
    const int n_per_batch = in_sizes[1] / B;

    fused_segenc_loss_kernel<<<1, 1024>>>(preds, targets, (float*)d_out,
                                          B, C, n_per_batch);
}

// round 4
// speedup vs baseline: 1.3462x; 1.0337x over previous
#include <cuda_runtime.h>
#include <cuda_bf16.h>

// Single fused kernel, single block of 512 threads, one warp per batch.
//
// Presence per batch decided from a 512-element sampled prefix (one warp x
// 4 int4 each). If the sampled mask is full, the remaining labels provably
// cannot change the (monotone) OR; miss prob ~2e-11/batch on random labels.
// Any batch whose sample is incomplete is fully scanned (correct for
// arbitrary inputs). Decision depends only on input data: deterministic.
//
// Cycle-path design (GPU idles at low clock during graph replay; wall time =
// critical-path cycles):
//  - __reduce_or_sync returns the warp's mask in EVERY lane -> each warp
//    checks its own saturation locally; lane 0 plain-stores smask[w].
//    No shared init, no shared atomics on the fast path.
//  - ONE __syncthreads_and serves as both the block-wide saturation decision
//    and the smask visibility barrier.
//  - BCE log-sigmoid terms computed from preds while targets loads are in
//    flight (transcendentals hidden under DRAM latency).

#define MAX_B 64

__global__ void fused_segenc_loss_kernel(const float* __restrict__ preds,
                                         const int*   __restrict__ targets,
                                         float* __restrict__ out,
                                         int B, int C, int n_per_batch) {
    __shared__ unsigned int smask[MAX_B];
    __shared__ float warp_sums[32];

    const int t    = threadIdx.x;
    const int w    = t >> 5;                 // warp id == batch id for sampling
    const int lane = t & 31;
    const int nwarps = blockDim.x >> 5;
    const unsigned int full_mask = (1u << C) - 1u;
    const bool vec_ok = ((n_per_batch & 3) == 0);
    const int total4 = n_per_batch >> 2;
    const int n = B * C;

    // ---- sample loads first (longest latency): 32 thr x 4 int4 = 512 ints
    unsigned int m = 0u;
    const bool sampler = (w < B) && vec_ok;
    if (sampler) {
        const int4* __restrict__ t4 =
            reinterpret_cast<const int4*>(targets) + (long long)w * total4;
        const int limit = min(128, total4);
        #pragma unroll
        for (int k = 0; k < 4; k++) {
            const int idx = lane + (k << 5);
            if (idx < limit) {
                const int4 v = t4[idx];
                m |= (1u << (v.x & 31)) | (1u << (v.y & 31)) |
                     (1u << (v.z & 31)) | (1u << (v.w & 31));
            }
        }
    }

    // ---- overlap: preds load + stable log-sigmoid (mask-independent)
    float lsp = 0.0f, lsn = 0.0f;
    int ib = 0;
    const bool has_elem = (t < n);
    if (has_elem) {
        const float x = preds[t];
        ib = t / C;
        const float l = log1pf(expf(-fabsf(x)));   // = -logsig(|x|)
        lsp = fminf(x, 0.0f) - l;                  // logsig(x)
        lsn = fminf(-x, 0.0f) - l;                 // logsig(-x)
    }

    // ---- warp-local mask + own saturation check (no shared traffic yet)
    int ok = 1;
    if (w < B) {
        const unsigned int wm = __reduce_or_sync(0xffffffffu, m);  // all lanes
        if (lane == 0) smask[w] = wm;
        ok = ((wm & full_mask) == full_mask);
    }
    // Batches beyond warp count (only if B > nwarps): zero their mask and
    // force the fallback to scan them.
    if (t >= nwarps && t < B) { smask[t] = 0u; ok = 0; }

    // ONE barrier: block-wide saturation decision + smask visibility.
    if (!__syncthreads_and(ok)) {
        // Rare fallback: full scalar scan of incomplete batches.
        // Block-uniform control flow (reads post-barrier shared state).
        for (int bb = 0; bb < B; bb++) {
            if ((smask[bb] & full_mask) != full_mask) {
                unsigned int mm = 0u;
                const int* __restrict__ tb = targets + (long long)bb * n_per_batch;
                for (int i = t; i < n_per_batch; i += blockDim.x)
                    mm |= 1u << (tb[i] & 31);
                const unsigned int wmm = __reduce_or_sync(0xffffffffu, mm);
                if ((t & 31) == 0) atomicOr(&smask[bb], wmm);
                __syncthreads();
            }
        }
        __syncthreads();
    }

    // ---- loss: select precomputed pieces by presence bit
    float acc = 0.0f;
    if (has_elem) {
        const int ic = t - ib * C;
        acc = -(((smask[ib] >> ic) & 1u) ? lsp : lsn);
    }
    // Generality: elements beyond blockDim (only if B*C > blockDim).
    for (int i = t + blockDim.x; i < n; i += blockDim.x) {
        const int ib2 = i / C;
        const int ic2 = i - ib2 * C;
        const float x = preds[i];
        const float l = log1pf(expf(-fabsf(x)));
        const float p = fminf(x, 0.0f) - l;
        const float q = fminf(-x, 0.0f) - l;
        acc += -(((smask[ib2] >> ic2) & 1u) ? p : q);
    }

    // ---- block reduction (16 warps)
    for (int off = 16; off > 0; off >>= 1)
        acc += __shfl_down_sync(0xffffffffu, acc, off);
    if (lane == 0) warp_sums[w] = acc;
    __syncthreads();
    if (t < 32) {
        float v = (t < nwarps) ? warp_sums[t] : 0.0f;
        for (int off = 16; off > 0; off >>= 1)
            v += __shfl_down_sync(0xffffffffu, v, off);
        if (t == 0) out[0] = v / (float)n;
    }
}

extern "C" void kernel_launch(void* const* d_in, const int* in_sizes, int n_in,
                              void* d_out, int out_size) {
    const float* preds   = (const float*)d_in[0];
    const int*   targets = (const int*)d_in[1];

    const int C = 19;                       // NUM_CLASSES (fixed by problem)
    const int B = in_sizes[0] / C;          // 16
    const int n_per_batch = in_sizes[1] / B;

    fused_segenc_loss_kernel<<<1, 512>>>(preds, targets, (float*)d_out,
                                         B, C, n_per_batch);
}